// round 15
// baseline (speedup 1.0000x reference)
#include <cuda_runtime.h>
#include <math.h>

#define H 768
#define H4 192
#define SEQ 512
#define VOC 30522
#define BATCH 8
#define TMAXX 32
#define EXT (VOC+SEQ)
#define X3H (3*H)
#define X3H4 (X3H/4)
#define NEGV -1e6f
#define D1 (BATCH*TMAXX*EXT)
#define NCTA 148
#define NTHR 512
#define NWARP 16
#define NW (NCTA*NWARP)          /* 2368 warps */
#define GWARPS 8                 /* gen warps per CTA (wid 0..7) */
#define NGW (NCTA*GWARPS)        /* 1184 gen warps */
#define GBLK3 (VOC/3)            /* 10174 gen blocks of 3 rows */
#define GQ4 3                    /* gen-block quota after P4 */
#define GQ5 7                    /* after P5 */
#define GQ6 8                    /* gen warps stop at 8 blocks = 9472 total */
#define GTAIL (NGW*GQ6)          /* 9472: tail blocks done by dot warps */
#define ZCH 207
#define MNEG (-3e38f)

/* smem float offsets */
#define SM_WBUF 0                       /* 8 warps * 2 bufs * 2304 floats = 36864 */
#define SM_HS   36864                   /* BATCH*H = 6144 floats */
#define SM_XCS  43008                   /* BATCH*2H = 12288 floats (ctx|sel) */
#define SM_TOTF 55296                   /* *4 = 221184 bytes */

// ---------------- persistent device scratch ----------------
__device__ __align__(16) float g_x[BATCH*X3H];     // [ - | - | emb]
__device__ __align__(16) float g_th[BATCH*H];
__device__ __align__(16) float g_th2[BATCH*H];
__device__ float g_sc[BATCH*SEQ];
__device__ float g_ws[BATCH*SEQ];
__device__ float g_invden[BATCH];
__device__ float g_css[BATCH*SEQ];
__device__ __align__(16) float g_selp[4][BATCH*H];
__device__ __align__(16) float g_ctxp[4][BATCH*H];
__device__ __align__(16) float g_ghv[3][BATCH][H];
__device__ __align__(16) float g_gI[3][BATCH][H];
__device__ float g_copyval[BATCH*VOC];
__device__ __align__(16) float g_gen[VOC*8];
__device__ unsigned long long g_amax2[BATCH];
__device__ float2 g_Zp2[NCTA][BATCH];
__device__ unsigned char g_present[BATCH*VOC];
__device__ unsigned char g_fo[BATCH*SEQ];
__device__ unsigned int g_bar;

__device__ __forceinline__ unsigned int okey(float f){
    unsigned int u = __float_as_uint(f);
    return (u & 0x80000000u) ? ~u : (u | 0x80000000u);
}
__device__ __forceinline__ float wred(float a){
    #pragma unroll
    for (int o = 16; o; o >>= 1) a += __shfl_xor_sync(0xffffffffu, a, o);
    return a;
}
__device__ __forceinline__ unsigned long long ffma2(unsigned long long a,
                                                    unsigned long long b,
                                                    unsigned long long c){
    unsigned long long d;
    asm("fma.rn.f32x2 %0, %1, %2, %3;" : "=l"(d) : "l"(a), "l"(b), "l"(c));
    return d;
}
__device__ __forceinline__ float hadd2(unsigned long long a){
    return __uint_as_float((unsigned int)a) + __uint_as_float((unsigned int)(a >> 32));
}
__device__ __forceinline__ void stcs(float* p, float v){
    asm volatile("st.global.cs.f32 [%0], %1;" :: "l"(p), "f"(v));
}
__device__ __forceinline__ float dot768_2(const void* __restrict__ A,
                                          const void* __restrict__ B, int lane){
    const ulonglong2* A2 = (const ulonglong2*)A;
    const ulonglong2* B2 = (const ulonglong2*)B;
    unsigned long long acc0 = 0ull, acc1 = 0ull;
    #pragma unroll
    for (int i = 0; i < 6; i++){
        ulonglong2 x = A2[i*32 + lane], y = B2[i*32 + lane];
        acc0 = ffma2(x.x, y.x, acc0);
        acc1 = ffma2(x.y, y.y, acc1);
    }
    return wred(hadd2(acc0) + hadd2(acc1));
}
__device__ __forceinline__ float gruc(float rr, float zz, float ni, float nh, float ho){
    float r = 1.f/(1.f + expf(-rr));
    float z = 1.f/(1.f + expf(-zz));
    float n = tanhf(ni + r*nh);
    return (1.f - z)*n + z*ho;
}
__device__ __forceinline__ void pmerge1(float &m, float &s, float g){
    float M = fmaxf(m, g);
    s = s*__expf(m - M) + __expf(g - M);
    m = M;
}
__device__ __forceinline__ void pmergep(float &m, float &s, float m2, float s2){
    float M = fmaxf(m, m2);
    s = s*__expf(m - M) + s2*__expf(m2 - M);
    m = M;
}
__device__ __forceinline__ void pshfl_reduce(float &m, float &s, int k){
    float mo = __shfl_xor_sync(0xffffffffu, m, k);
    float so = __shfl_xor_sync(0xffffffffu, s, k);
    pmergep(m, s, mo, so);
}
__device__ __forceinline__ float packred8(float* v, int lane){
    #pragma unroll
    for (int i = 0; i < 4; i++){
        float give = (lane & 4) ? v[i] : v[i+4];
        float got  = __shfl_xor_sync(0xffffffffu, give, 4);
        v[i] = ((lane & 4) ? v[i+4] : v[i]) + got;
    }
    #pragma unroll
    for (int i = 0; i < 2; i++){
        float give = (lane & 2) ? v[i] : v[i+2];
        float got  = __shfl_xor_sync(0xffffffffu, give, 2);
        v[i] = ((lane & 2) ? v[i+2] : v[i]) + got;
    }
    {
        float give = (lane & 1) ? v[0] : v[1];
        float got  = __shfl_xor_sync(0xffffffffu, give, 1);
        v[0] = ((lane & 1) ? v[1] : v[0]) + got;
    }
    v[0] += __shfl_xor_sync(0xffffffffu, v[0], 8);
    v[0] += __shfl_xor_sync(0xffffffffu, v[0], 16);
    return v[0];
}
// simple grid barrier — measured best (R5/R8/R12); do not replace
__device__ __forceinline__ void gridbar(unsigned int &target){
    __syncthreads();
    target += NCTA;
    if (threadIdx.x == 0){
        __threadfence();
        atomicAdd(&g_bar, 1u);
        while (*(volatile unsigned int*)&g_bar < target) __nanosleep(32);
        __threadfence();
    }
    __syncthreads();
}
// cp.async 16B (cg: L2 only)
__device__ __forceinline__ void cpa16(unsigned int dst, const void* src){
    asm volatile("cp.async.cg.shared.global [%0], [%1], 16;" :: "r"(dst), "l"(src));
}
// prefetch one 3-row gen block into a warp slot; ALWAYS commits a group
__device__ __forceinline__ void gen_prefetch(int blk, unsigned int slot_addr,
                                             const float* __restrict__ ow, int lane){
    if (blk < GBLK3){
        const char* src = (const char*)(ow + (size_t)blk*3*H);
        #pragma unroll
        for (int i = 0; i < 18; i++){
            int idx = i*32 + lane;
            cpa16(slot_addr + idx*16, src + (size_t)idx*16);
        }
    }
    asm volatile("cp.async.commit_group;" ::: "memory");
}

// ---------------- init (+ prep merged) ----------------
__global__ void k_init(const int* __restrict__ cls, const float* __restrict__ emb,
                       const float* __restrict__ ab, const int* __restrict__ inputs,
                       float* __restrict__ out, int has_tail){
    int i = blockIdx.x*blockDim.x + threadIdx.x;
    int n = gridDim.x*blockDim.x;
    if (i == 0) g_bar = 0u;
    for (int k = i; k < BATCH*EXT; k += n){
        int b = k/EXT, j = k - b*EXT;
        out[(size_t)b*TMAXX*EXT + j] = (j == 0) ? (float)(*cls) : 0.f;
    }
    const float L = logf(1e-10f);
    for (int k = i; k < BATCH*(TMAXX-1)*SEQ; k += n){
        int b = k/((TMAXX-1)*SEQ);
        int r = k - b*(TMAXX-1)*SEQ;
        int step = r/SEQ + 1;
        int s = r - (step-1)*SEQ;
        out[((size_t)b*TMAXX + step)*EXT + VOC + s] = L;
    }
    for (int k = i; k < BATCH*VOC; k += n) g_present[k] = 0;
    for (int k = i; k < 4*BATCH*H; k += n) g_selp[0][k] = 0.f;
    for (int k = i; k < BATCH*H; k += n){
        int b = k/H, j = k - b*H;
        g_x[b*X3H + 2*H + j] = emb[H + j];
        g_th[k] = ab[j];
    }
    if (i < BATCH) g_invden[i] = 1.f;
    if (has_tail && i < BATCH) out[D1 + i*TMAXX] = 1.0f;
    if (i < BATCH*SEQ){
        int b = i/SEQ, s = i - b*SEQ;
        const int* ip = inputs + b*SEQ;
        int t = ip[s];
        int fo = (t != 0);
        for (int s2 = 0; s2 < s; s2++) if (ip[s2] == t) fo = 0;
        g_fo[i] = (unsigned char)fo;
        if (fo) g_present[b*VOC + t] = 1;
    }
}

// gen compute: 3 rows x 8 batches, weights from a pointer (smem slot OR global),
// online Z. Same arithmetic order either way.
__device__ __forceinline__ void gen_compute3(int blk, const float* __restrict__ wsm,
                                             const float4* __restrict__ hs4s,
                                             const float* __restrict__ ob,
                                             int lane, float &zm, float &zs){
    int v0 = blk*3;
    const ulonglong2* W0 = (const ulonglong2*)(wsm);
    const ulonglong2* W1 = (const ulonglong2*)(wsm + H);
    const ulonglong2* W2 = (const ulonglong2*)(wsm + 2*H);
    const ulonglong2* HS = (const ulonglong2*)hs4s;
    unsigned long long a0[8], a1[8], a2[8];
    #pragma unroll
    for (int b2 = 0; b2 < 8; b2++){ a0[b2]=0ull; a1[b2]=0ull; a2[b2]=0ull; }
    #pragma unroll
    for (int i = 0; i < 6; i++){
        ulonglong2 w0 = W0[i*32 + lane], w1 = W1[i*32 + lane], w2 = W2[i*32 + lane];
        #pragma unroll
        for (int b2 = 0; b2 < 8; b2++){
            ulonglong2 h = HS[b2*H4 + i*32 + lane];
            a0[b2] = ffma2(w0.x, h.x, a0[b2]); a0[b2] = ffma2(w0.y, h.y, a0[b2]);
            a1[b2] = ffma2(w1.x, h.x, a1[b2]); a1[b2] = ffma2(w1.y, h.y, a1[b2]);
            a2[b2] = ffma2(w2.x, h.x, a2[b2]); a2[b2] = ffma2(w2.y, h.y, a2[b2]);
        }
    }
    float v[8], u[8], w[8];
    #pragma unroll
    for (int b2 = 0; b2 < 8; b2++){
        v[b2] = hadd2(a0[b2]); u[b2] = hadd2(a1[b2]); w[b2] = hadd2(a2[b2]);
    }
    float r0 = packred8(v, lane);
    float r1 = packred8(u, lane);
    float r2 = packred8(w, lane);
    int bb = lane & 7;
    if (lane < 8){
        float g = r0 + ob[v0];
        if (v0 == 0) g = NEGV;
        g_gen[(size_t)v0*8 + bb] = g;
        pmerge1(zm, zs, g);
    } else if (lane < 16){
        float g = r1 + ob[v0+1];
        g_gen[(size_t)(v0+1)*8 + bb] = g;
        pmerge1(zm, zs, g);
    } else if (lane < 24){
        float g = r2 + ob[v0+2];
        g_gen[(size_t)(v0+2)*8 + bb] = g;
        pmerge1(zm, zs, g);
    }
}

// ---------------- persistent decode loop ----------------
__global__ void __launch_bounds__(NTHR, 1)
k_loop(const float* __restrict__ enc, const int* __restrict__ inputs,
       const float* __restrict__ emb,
       const float4* __restrict__ aw4, const float* __restrict__ ab,
       const float4* __restrict__ cw4, const float* __restrict__ cb,
       const float4* __restrict__ wih4, const float4* __restrict__ whh4,
       const float* __restrict__ bih, const float* __restrict__ bhh,
       const float* __restrict__ ow, const float* __restrict__ ob,
       float* __restrict__ out, int has_tail)
{
    const int tid = threadIdx.x, cta = blockIdx.x;
    const int wid = tid >> 5, lane = tid & 31;
    const int W = cta*NWARP + wid;
    const int isgen = (wid < GWARPS);
    const int gw = cta*GWARPS + wid;
    const int dw = cta*GWARPS + (wid - GWARPS);
    unsigned int bt = 0;

    extern __shared__ float smem[];
    float4* hs4 = (float4*)(smem + SM_HS);
    float4* xcs = (float4*)(smem + SM_XCS);
    unsigned int slotA = 0, slotB = 0;
    if (isgen){
        slotA = (unsigned int)__cvta_generic_to_shared(smem + SM_WBUF + (wid*2+0)*(3*H));
        slotB = (unsigned int)__cvta_generic_to_shared(smem + SM_WBUF + (wid*2+1)*(3*H));
    }

    __shared__ float2 zsm[NWARP*8];
    __shared__ float zinv[8], msh[8];
    __shared__ unsigned long long bkey[8];

    for (int m = tid; m < BATCH*H4; m += NTHR) hs4[m] = make_float4(0.f,0.f,0.f,0.f);
    __syncthreads();

    for (int t = 1; t < TMAXX; t++){
        float zm = MNEG, zs = 0.f;
        int gk = 0;

        // ===== P1: attention scores (4096, th from L2) || finalize(t-1) (8)
        for (int task = W; task < 4096 + 8; task += NW){
            if (task < 4096){
                int b = task >> 9, s = task & 511;
                float a = dot768_2(enc + ((size_t)b*SEQ + s)*H, g_th + b*H, lane);
                if (!lane) g_sc[b*SEQ + s] = a;
            } else if (t > 1){
                int b = task - 4096;
                unsigned long long key = g_amax2[b];
                int samp = 0x7FFFFFFF - (int)(unsigned int)(key & 0xFFFFFFFFull);
                if (!lane && has_tail) out[D1 + b*TMAXX + (t-1)] = (float)samp;
                int kc = (samp > VOC) ? 3 : min(samp, VOC - 1);
                const float4* er = (const float4*)(emb + (size_t)kc*H);
                float4* xd = (float4*)(g_x + b*X3H + 2*H);
                #pragma unroll
                for (int i = 0; i < 6; i++) xd[lane + 32*i] = er[lane + 32*i];
                float ad = 0.f;
                #pragma unroll
                for (int i = 0; i < 16; i++){
                    int s = lane + 32*i;
                    float w = (inputs[b*SEQ + s] == samp) ? g_css[b*SEQ + s] : 0.f;
                    g_ws[b*SEQ + s] = w;
                    ad += fabsf(w);
                }
                ad = wred(ad);
                if (!lane) g_invden[b] = 1.f/fmaxf(ad, 1e-12f);
            }
        }
        gridbar(bt);

        // ===== P2: sel-read quarters (768, ILP8) + ctx quarters (768, ILP8) + reset
        for (int task = W; task < 1537; task += NW){
            if (task < 768){
                if (t > 1){
                    int b = task/96, r = task - b*96;
                    int hc = r >> 2, c4 = r & 3;
                    int h0 = hc*32 + lane, s0 = c4*128;
                    const float* ep = enc + ((size_t)b*SEQ + s0)*H + h0;
                    const float* wp = g_ws + b*SEQ + s0;
                    float a0=0,a1=0,a2=0,a3=0,a4=0,a5=0,a6=0,a7=0;
                    for (int s = 0; s < 128; s += 8){
                        a0 += wp[s+0]*ep[(size_t)(s+0)*H];
                        a1 += wp[s+1]*ep[(size_t)(s+1)*H];
                        a2 += wp[s+2]*ep[(size_t)(s+2)*H];
                        a3 += wp[s+3]*ep[(size_t)(s+3)*H];
                        a4 += wp[s+4]*ep[(size_t)(s+4)*H];
                        a5 += wp[s+5]*ep[(size_t)(s+5)*H];
                        a6 += wp[s+6]*ep[(size_t)(s+6)*H];
                        a7 += wp[s+7]*ep[(size_t)(s+7)*H];
                    }
                    g_selp[c4][b*H + h0] = ((a0+a1)+(a2+a3))+((a4+a5)+(a6+a7));
                }
            } else if (task < 1536){
                int id = task - 768;
                int b = id/96, r = id - b*96;
                int hc = r >> 2, q = r & 3;
                int h0 = hc*32 + lane;
                const float* sp = g_sc + b*SEQ;
                float mx = -1e30f;
                #pragma unroll
                for (int i = 0; i < 16; i++) mx = fmaxf(mx, sp[lane + 32*i]);
                #pragma unroll
                for (int o = 16; o; o >>= 1) mx = fmaxf(mx, __shfl_xor_sync(0xffffffffu, mx, o));
                float se = 0.f;
                #pragma unroll
                for (int i = 0; i < 16; i++) se += expf(sp[lane + 32*i] - mx);
                se = wred(se);
                float inv = 1.f/se;
                float a0=0,a1=0,a2=0,a3=0,a4=0,a5=0,a6=0,a7=0;
                const float* ep = enc + ((size_t)b*SEQ + q*128)*H + h0;
                const float* spq = sp + q*128;
                for (int s0 = 0; s0 < 128; s0 += 32){
                    float w = expf(spq[s0 + lane] - mx)*inv;
                    #pragma unroll
                    for (int i = 0; i < 32; i += 8){
                        a0 += __shfl_sync(0xffffffffu, w, i+0)*ep[(size_t)(s0+i+0)*H];
                        a1 += __shfl_sync(0xffffffffu, w, i+1)*ep[(size_t)(s0+i+1)*H];
                        a2 += __shfl_sync(0xffffffffu, w, i+2)*ep[(size_t)(s0+i+2)*H];
                        a3 += __shfl_sync(0xffffffffu, w, i+3)*ep[(size_t)(s0+i+3)*H];
                        a4 += __shfl_sync(0xffffffffu, w, i+4)*ep[(size_t)(s0+i+4)*H];
                        a5 += __shfl_sync(0xffffffffu, w, i+5)*ep[(size_t)(s0+i+5)*H];
                        a6 += __shfl_sync(0xffffffffu, w, i+6)*ep[(size_t)(s0+i+6)*H];
                        a7 += __shfl_sync(0xffffffffu, w, i+7)*ep[(size_t)(s0+i+7)*H];
                    }
                }
                g_ctxp[q][b*H + h0] = ((a0+a1)+(a2+a3))+((a4+a5)+(a6+a7));
            } else {
                if (lane < 8) g_amax2[lane] = 0ull;
            }
        }
        gridbar(bt);

        // ===== P3: stage combined ctx|sel to xcs; gi GRU (1152) + gh GRU (1152);
        //           gen warps kick off first weight prefetch
        {
            for (int m = tid; m < BATCH*2*H4; m += NTHR){
                int b = m / (2*H4), sl = m - b*(2*H4);
                float4 v;
                if (sl < H4){
                    int c = b*H4 + sl;
                    float4 p0 = ((const float4*)g_ctxp[0])[c];
                    float4 p1 = ((const float4*)g_ctxp[1])[c];
                    float4 p2 = ((const float4*)g_ctxp[2])[c];
                    float4 p3 = ((const float4*)g_ctxp[3])[c];
                    v.x = (p0.x+p1.x)+(p2.x+p3.x);
                    v.y = (p0.y+p1.y)+(p2.y+p3.y);
                    v.z = (p0.z+p1.z)+(p2.z+p3.z);
                    v.w = (p0.w+p1.w)+(p2.w+p3.w);
                } else {
                    int c = b*H4 + (sl - H4);
                    float4 p0 = ((const float4*)g_selp[0])[c];
                    float4 p1 = ((const float4*)g_selp[1])[c];
                    float4 p2 = ((const float4*)g_selp[2])[c];
                    float4 p3 = ((const float4*)g_selp[3])[c];
                    float inv = g_invden[b];
                    v.x = (p0.x+p1.x+p2.x+p3.x)*inv;
                    v.y = (p0.y+p1.y+p2.y+p3.y)*inv;
                    v.z = (p0.z+p1.z+p2.z+p3.z)*inv;
                    v.w = (p0.w+p1.w+p2.w+p3.w)*inv;
                }
                xcs[m] = v;
            }
            __syncthreads();
        }
        for (int task = W; task < 2304; task += NW){
            if (task < 1152){
                int r0 = task*2;
                const float4* wiA = wih4 + (size_t)r0*X3H4;
                const float4* wiB = wiA + X3H4;
                float giA[8]={0,0,0,0,0,0,0,0}, giB[8]={0,0,0,0,0,0,0,0};
                for (int i = 0; i < 18; i++){
                    float4 wa = wiA[i*32 + lane], wb = wiB[i*32 + lane];
                    int sl = i*32 + lane;
                    #pragma unroll
                    for (int b = 0; b < 8; b++){
                        float4 x = (sl < 2*H4) ? xcs[b*2*H4 + sl]
                                               : ((const float4*)g_x)[b*X3H4 + sl];
                        giA[b] += wa.x*x.x + wa.y*x.y + wa.z*x.z + wa.w*x.w;
                        giB[b] += wb.x*x.x + wb.y*x.y + wb.z*x.z + wb.w*x.w;
                    }
                }
                float rA = packred8(giA, lane);
                float rB = packred8(giB, lane);
                if (lane < 16){
                    int rr = (lane < 8) ? 0 : 1;
                    int r = r0 + rr;
                    int g = r/H, j = r - g*H;
                    float gi = (lane < 8) ? rA : rB;
                    g_gI[g][lane & 7][j] = gi + bih[r];
                }
            } else {
                int r0 = (task - 1152)*2;
                const float4* whA = whh4 + (size_t)r0*H4;
                const float4* whB = whA + H4;
                float ghA[8]={0,0,0,0,0,0,0,0}, ghB[8]={0,0,0,0,0,0,0,0};
                #pragma unroll
                for (int i = 0; i < 6; i++){
                    float4 wa = whA[i*32 + lane], wb = whB[i*32 + lane];
                    #pragma unroll
                    for (int b = 0; b < 8; b++){
                        float4 h = hs4[b*H4 + i*32 + lane];
                        ghA[b] += wa.x*h.x + wa.y*h.y + wa.z*h.z + wa.w*h.w;
                        ghB[b] += wb.x*h.x + wb.y*h.y + wb.z*h.z + wb.w*h.w;
                    }
                }
                float rA = packred8(ghA, lane);
                float rB = packred8(ghB, lane);
                if (lane < 16){
                    int rr = (lane < 8) ? 0 : 1;
                    int r = r0 + rr;
                    int g = r/H, j = r - g*H;
                    float gh = (lane < 8) ? rA : rB;
                    g_ghv[g][lane & 7][j] = gh + bhh[r];
                }
            }
        }
        if (isgen) gen_prefetch(gw, slotA, ow, lane);
        gridbar(bt);

        // ===== P4: combine h; gen warps: k<GQ4 | dot warps: th+th2 (3072)
        {
            for (int m = tid; m < BATCH*H4; m += NTHR){
                int b = m/H4, c = m - b*H4;
                float4 i0 = ((const float4*)g_gI[0][b])[c];
                float4 i1 = ((const float4*)g_gI[1][b])[c];
                float4 i2 = ((const float4*)g_gI[2][b])[c];
                float4 h0 = ((const float4*)g_ghv[0][b])[c];
                float4 h1 = ((const float4*)g_ghv[1][b])[c];
                float4 h2 = ((const float4*)g_ghv[2][b])[c];
                float4 ho = hs4[m];
                float4 hv;
                hv.x = gruc(i0.x+h0.x, i1.x+h1.x, i2.x, h2.x, ho.x);
                hv.y = gruc(i0.y+h0.y, i1.y+h1.y, i2.y, h2.y, ho.y);
                hv.z = gruc(i0.z+h0.z, i1.z+h1.z, i2.z, h2.z, ho.z);
                hv.w = gruc(i0.w+h0.w, i1.w+h1.w, i2.w, h2.w, ho.w);
                hs4[m] = hv;
            }
            __syncthreads();
        }
        if (isgen){
            while (gk < GQ4){
                int blk = gw + NGW*gk;
                gen_prefetch(gw + NGW*(gk+1), (gk & 1) ? slotA : slotB, ow, lane);
                asm volatile("cp.async.wait_group 1;" ::: "memory");
                __syncwarp();
                gen_compute3(blk, smem + SM_WBUF + (wid*2 + (gk&1))*(3*H),
                             hs4, ob, lane, zm, zs);
                gk++;
            }
        } else {
            for (int k = 0;; k++){
                int task = dw + NGW*k;
                if (task >= 3072) break;
                int is_th = (task >= 1536);
                int tt = is_th ? task - 1536 : task;
                int bh = tt & 1, j = tt >> 1;
                int b0 = bh*4;
                const ulonglong2* r2 = (const ulonglong2*)((is_th ? aw4 : cw4) + (size_t)j*H4);
                const ulonglong2* HS = (const ulonglong2*)hs4;
                unsigned long long a0=0ull, a1=0ull, a2=0ull, a3=0ull;
                #pragma unroll
                for (int i = 0; i < 6; i++){
                    ulonglong2 w = r2[i*32 + lane];
                    ulonglong2 h0 = HS[(b0+0)*H4 + i*32 + lane];
                    ulonglong2 h1 = HS[(b0+1)*H4 + i*32 + lane];
                    ulonglong2 h2 = HS[(b0+2)*H4 + i*32 + lane];
                    ulonglong2 h3 = HS[(b0+3)*H4 + i*32 + lane];
                    a0 = ffma2(w.x, h0.x, a0); a0 = ffma2(w.y, h0.y, a0);
                    a1 = ffma2(w.x, h1.x, a1); a1 = ffma2(w.y, h1.y, a1);
                    a2 = ffma2(w.x, h2.x, a2); a2 = ffma2(w.y, h2.y, a2);
                    a3 = ffma2(w.x, h3.x, a3); a3 = ffma2(w.y, h3.y, a3);
                }
                float f0 = wred(hadd2(a0)), f1 = wred(hadd2(a1));
                float f2 = wred(hadd2(a2)), f3 = wred(hadd2(a3));
                if (!lane){
                    float bb = is_th ? ab[j] : cb[j];
                    float* dst = is_th ? g_th : g_th2;
                    dst[(b0+0)*H + j] = f0 + bb;
                    dst[(b0+1)*H + j] = f1 + bb;
                    dst[(b0+2)*H + j] = f2 + bb;
                    dst[(b0+3)*H + j] = f3 + bb;
                }
            }
        }
        gridbar(bt);

        // ===== P5: gen warps: k<GQ5 | dot warps: css (4096, th2 from L2)
        if (isgen){
            while (gk < GQ5){
                int blk = gw + NGW*gk;
                gen_prefetch(gw + NGW*(gk+1), (gk & 1) ? slotA : slotB, ow, lane);
                asm volatile("cp.async.wait_group 1;" ::: "memory");
                __syncwarp();
                gen_compute3(blk, smem + SM_WBUF + (wid*2 + (gk&1))*(3*H),
                             hs4, ob, lane, zm, zs);
                gk++;
            }
        } else {
            for (int k = 0;; k++){
                int task = dw + NGW*k;
                if (task >= 4096) break;
                int b = task >> 9, s = task & 511;
                float a = dot768_2(enc + ((size_t)b*SEQ + s)*H, g_th2 + b*H, lane);
                if (!lane) g_css[b*SEQ + s] = a;
            }
        }
        gridbar(bt);

        // ===== P6: gen warps: finish to GQ6 | dot warps: copy-chain (128) +
        //           gen TAIL (blocks >= GTAIL, weights straight from global); CTA Z
        if (isgen){
            while (gk < GQ6){
                int blk = gw + NGW*gk;
                gen_prefetch(gw + NGW*(gk+1), (gk & 1) ? slotA : slotB, ow, lane);
                asm volatile("cp.async.wait_group 1;" ::: "memory");
                __syncwarp();
                gen_compute3(blk, smem + SM_WBUF + (wid*2 + (gk&1))*(3*H),
                             hs4, ob, lane, zm, zs);
                gk++;
            }
            asm volatile("cp.async.wait_group 0;" ::: "memory");
        } else {
            if (dw < 128){
                int b = dw >> 4, ch = dw & 15;
                int s = ch*32 + lane;
                float cm = MNEG, cs = 0.f;
                if (g_fo[b*SEQ + s]){
                    int tok = inputs[b*SEQ + s];
                    const int* ip = inputs + b*SEQ;
                    const float* cp = g_css + b*SEQ;
                    float sum = 0.f;
                    for (int s2 = 0; s2 < SEQ; s2++)
                        if (ip[s2] == tok) sum += cp[s2];
                    g_copyval[b*VOC + tok] = sum;
                    pmerge1(cm, cs, sum);
                }
                pshfl_reduce(cm, cs, 16);
                pshfl_reduce(cm, cs, 8);
                pshfl_reduce(cm, cs, 4);
                pshfl_reduce(cm, cs, 2);
                pshfl_reduce(cm, cs, 1);
                if (lane == b) pmergep(zm, zs, cm, cs);
            }
            // gen tail: 702 blocks, weights via plain global loads (L2/DRAM)
            {
                int blk = GTAIL + dw;
                if (blk < GBLK3)
                    gen_compute3(blk, ow + (size_t)blk*3*H, hs4, ob, lane, zm, zs);
            }
        }
        pshfl_reduce(zm, zs, 8);
        pshfl_reduce(zm, zs, 16);
        if (lane < 8) zsm[wid*8 + lane] = make_float2(zm, zs);
        __syncthreads();
        if (wid < 8){
            float2 p = (lane < NWARP) ? zsm[lane*8 + wid] : make_float2(MNEG, 0.f);
            float m = p.x, s = p.y;
            pshfl_reduce(m, s, 16);
            pshfl_reduce(m, s, 8);
            pshfl_reduce(m, s, 4);
            pshfl_reduce(m, s, 2);
            pshfl_reduce(m, s, 1);
            if (!lane) g_Zp2[cta][wid] = make_float2(m, s);
        }
        gridbar(bt);

        // ===== P7: global Z combine; log-prob row + argmax (streaming stores)
        {
            if (tid < 8) bkey[tid] = 0ull;
            if (wid < 8){
                float m = MNEG, s = 0.f;
                for (int i = lane; i < NCTA; i += 32){
                    float2 p = g_Zp2[i][wid];
                    pmergep(m, s, p.x, p.y);
                }
                pshfl_reduce(m, s, 16);
                pshfl_reduce(m, s, 8);
                pshfl_reduce(m, s, 4);
                pshfl_reduce(m, s, 2);
                pshfl_reduce(m, s, 1);
                if (!lane){ msh[wid] = m; zinv[wid] = 1.f/s; }
            }
            __syncthreads();
            int v0 = cta*ZCH;
            int cnt = min(ZCH, VOC - v0);
            if (tid < cnt){
                int v = v0 + tid;
                float4 a = ((const float4*)g_gen)[(size_t)v*2];
                float4 c = ((const float4*)g_gen)[(size_t)v*2 + 1];
                float gv[8] = {a.x, a.y, a.z, a.w, c.x, c.y, c.z, c.w};
                unsigned int vk = (unsigned int)(0x7FFFFFFF - v);
                #pragma unroll
                for (int b = 0; b < 8; b++){
                    float p = __expf(gv[b] - msh[b])*zinv[b];
                    if (g_present[b*VOC + v])
                        p += __expf(g_copyval[b*VOC + v] - msh[b])*zinv[b];
                    float lp = __logf(p + 1e-10f);
                    stcs(out + ((size_t)b*TMAXX + t)*EXT + v, lp);
                    unsigned long long key = (((unsigned long long)okey(lp)) << 32) | vk;
                    atomicMax(&bkey[b], key);
                }
            }
            __syncthreads();
            if (tid < 8) atomicMax(&g_amax2[tid], bkey[tid]);
        }
        gridbar(bt);
    }

    if (cta == 0 && tid < 8 && has_tail){
        unsigned long long key = g_amax2[tid];
        int samp = 0x7FFFFFFF - (int)(unsigned int)(key & 0xFFFFFFFFull);
        out[D1 + tid*TMAXX + (TMAXX - 1)] = (float)samp;
    }
}

// ---------------- host ----------------
extern "C" void kernel_launch(void* const* d_in, const int* in_sizes, int n_in,
                              void* d_out, int out_size){
    const float* enc    = (const float*)d_in[0];
    const int*   inputs = (const int*)  d_in[1];
    const int*   cls    = (const int*)  d_in[2];
    /* d_in[3] sep_to unused */
    const float* emb    = (const float*)d_in[4];
    const float* aw     = (const float*)d_in[5];
    const float* ab     = (const float*)d_in[6];
    const float* cw     = (const float*)d_in[7];
    const float* cb     = (const float*)d_in[8];
    const float* wih    = (const float*)d_in[9];
    const float* whh    = (const float*)d_in[10];
    const float* bih    = (const float*)d_in[11];
    const float* bhh    = (const float*)d_in[12];
    const float* ow     = (const float*)d_in[13];
    const float* ob     = (const float*)d_in[14];
    float* out = (float*)d_out;
    int has_tail = (out_size >= D1 + BATCH*TMAXX) ? 1 : 0;

    const int smemsz = SM_TOTF*sizeof(float);   // 221184 B
    cudaFuncSetAttribute(k_loop, cudaFuncAttributeMaxDynamicSharedMemorySize, smemsz);

    k_init<<<512, 256>>>(cls, emb, ab, inputs, out, has_tail);
    k_loop<<<NCTA, NTHR, smemsz>>>(enc, inputs, emb,
                                   (const float4*)aw, ab,
                                   (const float4*)cw, cb,
                                   (const float4*)wih, (const float4*)whh,
                                   bih, bhh,
                                   ow, ob,
                                   out, has_tail);
}

// round 16
// speedup vs baseline: 1.1385x; 1.1385x over previous
#include <cuda_runtime.h>
#include <math.h>

#define H 768
#define H4 192
#define SEQ 512
#define VOC 30522
#define BATCH 8
#define TMAXX 32
#define EXT (VOC+SEQ)
#define X3H (3*H)
#define X3H4 (X3H/4)
#define NEGV -1e6f
#define D1 (BATCH*TMAXX*EXT)
#define NCTA 148
#define NTHR 512
#define NWARP 16
#define NW (NCTA*NWARP)          /* 2368 warps */
#define GWARPS 8                 /* gen warps per CTA (wid 0..7) */
#define NGW (NCTA*GWARPS)        /* 1184 gen warps */
#define GBLK3 (VOC/3)            /* 10174 gen blocks of 3 rows */
#define GQ4 3                    /* gen-block quota after P4 */
#define GQ5 7                    /* after P5 */
#define GQ6 16                   /* after P6 (covers max 9) */
#define ZCH 207
#define MNEG (-3e38f)

/* smem float offsets */
#define SM_WBUF 0                       /* 8 warps * 2 bufs * 2304 floats = 36864 */
#define SM_HS   36864                   /* BATCH*H = 6144 floats */
#define SM_XCS  43008                   /* BATCH*2H = 12288 floats (ctx|sel) */
#define SM_TOTF 55296                   /* *4 = 221184 bytes */

// ---------------- persistent device scratch ----------------
__device__ __align__(16) float g_x[BATCH*X3H];     // [ - | - | emb]
__device__ __align__(16) float g_th[BATCH*H];
__device__ __align__(16) float g_th2[BATCH*H];
__device__ float g_sc[BATCH*SEQ];
__device__ float g_ws[BATCH*SEQ];
__device__ float g_invden[BATCH];
__device__ float g_css[BATCH*SEQ];
__device__ __align__(16) float g_selp[4][BATCH*H];
__device__ __align__(16) float g_ctxp[4][BATCH*H];
__device__ __align__(16) float g_ghv[3][BATCH][H];
__device__ __align__(16) float g_gI[3][BATCH][H];
__device__ float g_copyval[BATCH*VOC];
__device__ __align__(16) float g_gen[VOC*8];
__device__ unsigned long long g_amax2[BATCH];
__device__ float2 g_Zp2[NCTA][BATCH];
__device__ unsigned char g_present[BATCH*VOC];
__device__ unsigned char g_fo[BATCH*SEQ];
__device__ unsigned int g_bar;

__device__ __forceinline__ unsigned int okey(float f){
    unsigned int u = __float_as_uint(f);
    return (u & 0x80000000u) ? ~u : (u | 0x80000000u);
}
__device__ __forceinline__ float wred(float a){
    #pragma unroll
    for (int o = 16; o; o >>= 1) a += __shfl_xor_sync(0xffffffffu, a, o);
    return a;
}
__device__ __forceinline__ unsigned long long ffma2(unsigned long long a,
                                                    unsigned long long b,
                                                    unsigned long long c){
    unsigned long long d;
    asm("fma.rn.f32x2 %0, %1, %2, %3;" : "=l"(d) : "l"(a), "l"(b), "l"(c));
    return d;
}
__device__ __forceinline__ float hadd2(unsigned long long a){
    return __uint_as_float((unsigned int)a) + __uint_as_float((unsigned int)(a >> 32));
}
__device__ __forceinline__ void stcs(float* p, float v){
    asm volatile("st.global.cs.f32 [%0], %1;" :: "l"(p), "f"(v));
}
__device__ __forceinline__ float dot768_2(const void* __restrict__ A,
                                          const void* __restrict__ B, int lane){
    const ulonglong2* A2 = (const ulonglong2*)A;
    const ulonglong2* B2 = (const ulonglong2*)B;
    unsigned long long acc0 = 0ull, acc1 = 0ull;
    #pragma unroll
    for (int i = 0; i < 6; i++){
        ulonglong2 x = A2[i*32 + lane], y = B2[i*32 + lane];
        acc0 = ffma2(x.x, y.x, acc0);
        acc1 = ffma2(x.y, y.y, acc1);
    }
    return wred(hadd2(acc0) + hadd2(acc1));
}
__device__ __forceinline__ float gruc(float rr, float zz, float ni, float nh, float ho){
    float r = 1.f/(1.f + expf(-rr));
    float z = 1.f/(1.f + expf(-zz));
    float n = tanhf(ni + r*nh);
    return (1.f - z)*n + z*ho;
}
__device__ __forceinline__ void pmerge1(float &m, float &s, float g){
    float M = fmaxf(m, g);
    s = s*__expf(m - M) + __expf(g - M);
    m = M;
}
__device__ __forceinline__ void pmergep(float &m, float &s, float m2, float s2){
    float M = fmaxf(m, m2);
    s = s*__expf(m - M) + s2*__expf(m2 - M);
    m = M;
}
__device__ __forceinline__ void pshfl_reduce(float &m, float &s, int k){
    float mo = __shfl_xor_sync(0xffffffffu, m, k);
    float so = __shfl_xor_sync(0xffffffffu, s, k);
    pmergep(m, s, mo, so);
}
__device__ __forceinline__ float packred8(float* v, int lane){
    #pragma unroll
    for (int i = 0; i < 4; i++){
        float give = (lane & 4) ? v[i] : v[i+4];
        float got  = __shfl_xor_sync(0xffffffffu, give, 4);
        v[i] = ((lane & 4) ? v[i+4] : v[i]) + got;
    }
    #pragma unroll
    for (int i = 0; i < 2; i++){
        float give = (lane & 2) ? v[i] : v[i+2];
        float got  = __shfl_xor_sync(0xffffffffu, give, 2);
        v[i] = ((lane & 2) ? v[i+2] : v[i]) + got;
    }
    {
        float give = (lane & 1) ? v[0] : v[1];
        float got  = __shfl_xor_sync(0xffffffffu, give, 1);
        v[0] = ((lane & 1) ? v[1] : v[0]) + got;
    }
    v[0] += __shfl_xor_sync(0xffffffffu, v[0], 8);
    v[0] += __shfl_xor_sync(0xffffffffu, v[0], 16);
    return v[0];
}
// simple grid barrier — measured best (R5/R8/R12/R13); do not replace
__device__ __forceinline__ void gridbar(unsigned int &target){
    __syncthreads();
    target += NCTA;
    if (threadIdx.x == 0){
        __threadfence();
        atomicAdd(&g_bar, 1u);
        while (*(volatile unsigned int*)&g_bar < target) __nanosleep(32);
        __threadfence();
    }
    __syncthreads();
}
// cp.async 16B (cg: L2 only)
__device__ __forceinline__ void cpa16(unsigned int dst, const void* src){
    asm volatile("cp.async.cg.shared.global [%0], [%1], 16;" :: "r"(dst), "l"(src));
}
// prefetch one 3-row gen block into a warp slot; ALWAYS commits a group
__device__ __forceinline__ void gen_prefetch(int blk, unsigned int slot_addr,
                                             const float* __restrict__ ow, int lane){
    if (blk < GBLK3){
        const char* src = (const char*)(ow + (size_t)blk*3*H);
        #pragma unroll
        for (int i = 0; i < 18; i++){
            int idx = i*32 + lane;
            cpa16(slot_addr + idx*16, src + (size_t)idx*16);
        }
    }
    asm volatile("cp.async.commit_group;" ::: "memory");
}

// ---------------- init (+ prep merged) ----------------
__global__ void k_init(const int* __restrict__ cls, const float* __restrict__ emb,
                       const float* __restrict__ ab, const int* __restrict__ inputs,
                       float* __restrict__ out, int has_tail){
    int i = blockIdx.x*blockDim.x + threadIdx.x;
    int n = gridDim.x*blockDim.x;
    if (i == 0) g_bar = 0u;
    for (int k = i; k < BATCH*EXT; k += n){
        int b = k/EXT, j = k - b*EXT;
        out[(size_t)b*TMAXX*EXT + j] = (j == 0) ? (float)(*cls) : 0.f;
    }
    const float L = logf(1e-10f);
    for (int k = i; k < BATCH*(TMAXX-1)*SEQ; k += n){
        int b = k/((TMAXX-1)*SEQ);
        int r = k - b*(TMAXX-1)*SEQ;
        int step = r/SEQ + 1;
        int s = r - (step-1)*SEQ;
        out[((size_t)b*TMAXX + step)*EXT + VOC + s] = L;
    }
    for (int k = i; k < BATCH*VOC; k += n) g_present[k] = 0;
    for (int k = i; k < 4*BATCH*H; k += n) g_selp[0][k] = 0.f;
    for (int k = i; k < BATCH*H; k += n){
        int b = k/H, j = k - b*H;
        g_x[b*X3H + 2*H + j] = emb[H + j];
        g_th[k] = ab[j];
    }
    if (i < BATCH) g_invden[i] = 1.f;
    if (has_tail && i < BATCH) out[D1 + i*TMAXX] = 1.0f;
    if (i < BATCH*SEQ){
        int b = i/SEQ, s = i - b*SEQ;
        const int* ip = inputs + b*SEQ;
        int t = ip[s];
        int fo = (t != 0);
        for (int s2 = 0; s2 < s; s2++) if (ip[s2] == t) fo = 0;
        g_fo[i] = (unsigned char)fo;
        if (fo) g_present[b*VOC + t] = 1;
    }
}

// gen compute: 3 rows x 8 batches, weights from smem slot, online Z
__device__ __forceinline__ void gen_compute3(int blk, const float* __restrict__ wsm,
                                             const float4* __restrict__ hs4s,
                                             const float* __restrict__ ob,
                                             int lane, float &zm, float &zs){
    int v0 = blk*3;
    const ulonglong2* W0 = (const ulonglong2*)(wsm);
    const ulonglong2* W1 = (const ulonglong2*)(wsm + H);
    const ulonglong2* W2 = (const ulonglong2*)(wsm + 2*H);
    const ulonglong2* HS = (const ulonglong2*)hs4s;
    unsigned long long a0[8], a1[8], a2[8];
    #pragma unroll
    for (int b2 = 0; b2 < 8; b2++){ a0[b2]=0ull; a1[b2]=0ull; a2[b2]=0ull; }
    #pragma unroll
    for (int i = 0; i < 6; i++){
        ulonglong2 w0 = W0[i*32 + lane], w1 = W1[i*32 + lane], w2 = W2[i*32 + lane];
        #pragma unroll
        for (int b2 = 0; b2 < 8; b2++){
            ulonglong2 h = HS[b2*H4 + i*32 + lane];
            a0[b2] = ffma2(w0.x, h.x, a0[b2]); a0[b2] = ffma2(w0.y, h.y, a0[b2]);
            a1[b2] = ffma2(w1.x, h.x, a1[b2]); a1[b2] = ffma2(w1.y, h.y, a1[b2]);
            a2[b2] = ffma2(w2.x, h.x, a2[b2]); a2[b2] = ffma2(w2.y, h.y, a2[b2]);
        }
    }
    float v[8], u[8], w[8];
    #pragma unroll
    for (int b2 = 0; b2 < 8; b2++){
        v[b2] = hadd2(a0[b2]); u[b2] = hadd2(a1[b2]); w[b2] = hadd2(a2[b2]);
    }
    float r0 = packred8(v, lane);
    float r1 = packred8(u, lane);
    float r2 = packred8(w, lane);
    int bb = lane & 7;
    if (lane < 8){
        float g = r0 + ob[v0];
        if (v0 == 0) g = NEGV;
        g_gen[(size_t)v0*8 + bb] = g;
        pmerge1(zm, zs, g);
    } else if (lane < 16){
        float g = r1 + ob[v0+1];
        g_gen[(size_t)(v0+1)*8 + bb] = g;
        pmerge1(zm, zs, g);
    } else if (lane < 24){
        float g = r2 + ob[v0+2];
        g_gen[(size_t)(v0+2)*8 + bb] = g;
        pmerge1(zm, zs, g);
    }
}

// ---------------- persistent decode loop ----------------
__global__ void __launch_bounds__(NTHR, 1)
k_loop(const float* __restrict__ enc, const int* __restrict__ inputs,
       const float* __restrict__ emb,
       const float4* __restrict__ aw4, const float* __restrict__ ab,
       const float4* __restrict__ cw4, const float* __restrict__ cb,
       const float4* __restrict__ wih4, const float4* __restrict__ whh4,
       const float* __restrict__ bih, const float* __restrict__ bhh,
       const float* __restrict__ ow, const float* __restrict__ ob,
       float* __restrict__ out, int has_tail)
{
    const int tid = threadIdx.x, cta = blockIdx.x;
    const int wid = tid >> 5, lane = tid & 31;
    const int W = cta*NWARP + wid;
    const int isgen = (wid < GWARPS);
    const int gw = cta*GWARPS + wid;
    const int dw = cta*GWARPS + (wid - GWARPS);
    unsigned int bt = 0;

    extern __shared__ float smem[];
    float4* hs4 = (float4*)(smem + SM_HS);
    float4* xcs = (float4*)(smem + SM_XCS);
    unsigned int slotA = 0, slotB = 0;
    if (isgen){
        slotA = (unsigned int)__cvta_generic_to_shared(smem + SM_WBUF + (wid*2+0)*(3*H));
        slotB = (unsigned int)__cvta_generic_to_shared(smem + SM_WBUF + (wid*2+1)*(3*H));
    }

    __shared__ float2 zsm[NWARP*8];
    __shared__ float zinv[8], msh[8];
    __shared__ unsigned long long bkey[8];

    for (int m = tid; m < BATCH*H4; m += NTHR) hs4[m] = make_float4(0.f,0.f,0.f,0.f);
    __syncthreads();

    for (int t = 1; t < TMAXX; t++){
        float zm = MNEG, zs = 0.f;
        int gk = 0;

        // ===== P1: attention scores (4096, th from L2) || finalize(t-1) (8)
        for (int task = W; task < 4096 + 8; task += NW){
            if (task < 4096){
                int b = task >> 9, s = task & 511;
                float a = dot768_2(enc + ((size_t)b*SEQ + s)*H, g_th + b*H, lane);
                if (!lane) g_sc[b*SEQ + s] = a;
            } else if (t > 1){
                int b = task - 4096;
                unsigned long long key = g_amax2[b];
                int samp = 0x7FFFFFFF - (int)(unsigned int)(key & 0xFFFFFFFFull);
                if (!lane && has_tail) out[D1 + b*TMAXX + (t-1)] = (float)samp;
                int kc = (samp > VOC) ? 3 : min(samp, VOC - 1);
                const float4* er = (const float4*)(emb + (size_t)kc*H);
                float4* xd = (float4*)(g_x + b*X3H + 2*H);
                #pragma unroll
                for (int i = 0; i < 6; i++) xd[lane + 32*i] = er[lane + 32*i];
                float ad = 0.f;
                #pragma unroll
                for (int i = 0; i < 16; i++){
                    int s = lane + 32*i;
                    float w = (inputs[b*SEQ + s] == samp) ? g_css[b*SEQ + s] : 0.f;
                    g_ws[b*SEQ + s] = w;
                    ad += fabsf(w);
                }
                ad = wred(ad);
                if (!lane) g_invden[b] = 1.f/fmaxf(ad, 1e-12f);
            }
        }
        gridbar(bt);

        // ===== P2: sel-read quarters (768, ILP4) + ctx quarters (768, ILP4) + reset
        for (int task = W; task < 1537; task += NW){
            if (task < 768){
                if (t > 1){
                    int b = task/96, r = task - b*96;
                    int hc = r >> 2, c4 = r & 3;
                    int h0 = hc*32 + lane, s0 = c4*128;
                    const float* ep = enc + ((size_t)b*SEQ + s0)*H + h0;
                    const float* wp = g_ws + b*SEQ + s0;
                    float a0=0,a1=0,a2=0,a3=0;
                    for (int s = 0; s < 128; s += 4){
                        a0 += wp[s+0]*ep[(size_t)(s+0)*H];
                        a1 += wp[s+1]*ep[(size_t)(s+1)*H];
                        a2 += wp[s+2]*ep[(size_t)(s+2)*H];
                        a3 += wp[s+3]*ep[(size_t)(s+3)*H];
                    }
                    g_selp[c4][b*H + h0] = (a0+a1)+(a2+a3);
                }
            } else if (task < 1536){
                int id = task - 768;
                int b = id/96, r = id - b*96;
                int hc = r >> 2, q = r & 3;
                int h0 = hc*32 + lane;
                const float* sp = g_sc + b*SEQ;
                float mx = -1e30f;
                #pragma unroll
                for (int i = 0; i < 16; i++) mx = fmaxf(mx, sp[lane + 32*i]);
                #pragma unroll
                for (int o = 16; o; o >>= 1) mx = fmaxf(mx, __shfl_xor_sync(0xffffffffu, mx, o));
                float se = 0.f;
                #pragma unroll
                for (int i = 0; i < 16; i++) se += expf(sp[lane + 32*i] - mx);
                se = wred(se);
                float inv = 1.f/se;
                float a0=0,a1=0,a2=0,a3=0;
                const float* ep = enc + ((size_t)b*SEQ + q*128)*H + h0;
                const float* spq = sp + q*128;
                for (int s0 = 0; s0 < 128; s0 += 32){
                    float w = expf(spq[s0 + lane] - mx)*inv;
                    #pragma unroll
                    for (int i = 0; i < 32; i += 4){
                        a0 += __shfl_sync(0xffffffffu, w, i+0)*ep[(size_t)(s0+i+0)*H];
                        a1 += __shfl_sync(0xffffffffu, w, i+1)*ep[(size_t)(s0+i+1)*H];
                        a2 += __shfl_sync(0xffffffffu, w, i+2)*ep[(size_t)(s0+i+2)*H];
                        a3 += __shfl_sync(0xffffffffu, w, i+3)*ep[(size_t)(s0+i+3)*H];
                    }
                }
                g_ctxp[q][b*H + h0] = (a0+a1)+(a2+a3);
            } else {
                if (lane < 8) g_amax2[lane] = 0ull;
            }
        }
        gridbar(bt);

        // ===== P3: stage combined ctx|sel to xcs; gi GRU (1152) + gh GRU (1152);
        //           gen warps kick off first weight prefetch
        {
            for (int m = tid; m < BATCH*2*H4; m += NTHR){
                int b = m / (2*H4), sl = m - b*(2*H4);
                float4 v;
                if (sl < H4){
                    int c = b*H4 + sl;
                    float4 p0 = ((const float4*)g_ctxp[0])[c];
                    float4 p1 = ((const float4*)g_ctxp[1])[c];
                    float4 p2 = ((const float4*)g_ctxp[2])[c];
                    float4 p3 = ((const float4*)g_ctxp[3])[c];
                    v.x = (p0.x+p1.x)+(p2.x+p3.x);
                    v.y = (p0.y+p1.y)+(p2.y+p3.y);
                    v.z = (p0.z+p1.z)+(p2.z+p3.z);
                    v.w = (p0.w+p1.w)+(p2.w+p3.w);
                } else {
                    int c = b*H4 + (sl - H4);
                    float4 p0 = ((const float4*)g_selp[0])[c];
                    float4 p1 = ((const float4*)g_selp[1])[c];
                    float4 p2 = ((const float4*)g_selp[2])[c];
                    float4 p3 = ((const float4*)g_selp[3])[c];
                    float inv = g_invden[b];
                    v.x = (p0.x+p1.x+p2.x+p3.x)*inv;
                    v.y = (p0.y+p1.y+p2.y+p3.y)*inv;
                    v.z = (p0.z+p1.z+p2.z+p3.z)*inv;
                    v.w = (p0.w+p1.w+p2.w+p3.w)*inv;
                }
                xcs[m] = v;
            }
            __syncthreads();
        }
        for (int task = W; task < 2304; task += NW){
            if (task < 1152){
                int r0 = task*2;
                const float4* wiA = wih4 + (size_t)r0*X3H4;
                const float4* wiB = wiA + X3H4;
                float giA[8]={0,0,0,0,0,0,0,0}, giB[8]={0,0,0,0,0,0,0,0};
                for (int i = 0; i < 18; i++){
                    float4 wa = wiA[i*32 + lane], wb = wiB[i*32 + lane];
                    int sl = i*32 + lane;
                    #pragma unroll
                    for (int b = 0; b < 8; b++){
                        float4 x = (sl < 2*H4) ? xcs[b*2*H4 + sl]
                                               : ((const float4*)g_x)[b*X3H4 + sl];
                        giA[b] += wa.x*x.x + wa.y*x.y + wa.z*x.z + wa.w*x.w;
                        giB[b] += wb.x*x.x + wb.y*x.y + wb.z*x.z + wb.w*x.w;
                    }
                }
                float rA = packred8(giA, lane);
                float rB = packred8(giB, lane);
                if (lane < 16){
                    int rr = (lane < 8) ? 0 : 1;
                    int r = r0 + rr;
                    int g = r/H, j = r - g*H;
                    float gi = (lane < 8) ? rA : rB;
                    g_gI[g][lane & 7][j] = gi + bih[r];
                }
            } else {
                int r0 = (task - 1152)*2;
                const float4* whA = whh4 + (size_t)r0*H4;
                const float4* whB = whA + H4;
                float ghA[8]={0,0,0,0,0,0,0,0}, ghB[8]={0,0,0,0,0,0,0,0};
                #pragma unroll
                for (int i = 0; i < 6; i++){
                    float4 wa = whA[i*32 + lane], wb = whB[i*32 + lane];
                    #pragma unroll
                    for (int b = 0; b < 8; b++){
                        float4 h = hs4[b*H4 + i*32 + lane];
                        ghA[b] += wa.x*h.x + wa.y*h.y + wa.z*h.z + wa.w*h.w;
                        ghB[b] += wb.x*h.x + wb.y*h.y + wb.z*h.z + wb.w*h.w;
                    }
                }
                float rA = packred8(ghA, lane);
                float rB = packred8(ghB, lane);
                if (lane < 16){
                    int rr = (lane < 8) ? 0 : 1;
                    int r = r0 + rr;
                    int g = r/H, j = r - g*H;
                    float gh = (lane < 8) ? rA : rB;
                    g_ghv[g][lane & 7][j] = gh + bhh[r];
                }
            }
        }
        if (isgen) gen_prefetch(gw, slotA, ow, lane);
        gridbar(bt);

        // ===== P4: combine h; gen warps: k<GQ4 | dot warps: th+th2 (3072)
        {
            for (int m = tid; m < BATCH*H4; m += NTHR){
                int b = m/H4, c = m - b*H4;
                float4 i0 = ((const float4*)g_gI[0][b])[c];
                float4 i1 = ((const float4*)g_gI[1][b])[c];
                float4 i2 = ((const float4*)g_gI[2][b])[c];
                float4 h0 = ((const float4*)g_ghv[0][b])[c];
                float4 h1 = ((const float4*)g_ghv[1][b])[c];
                float4 h2 = ((const float4*)g_ghv[2][b])[c];
                float4 ho = hs4[m];
                float4 hv;
                hv.x = gruc(i0.x+h0.x, i1.x+h1.x, i2.x, h2.x, ho.x);
                hv.y = gruc(i0.y+h0.y, i1.y+h1.y, i2.y, h2.y, ho.y);
                hv.z = gruc(i0.z+h0.z, i1.z+h1.z, i2.z, h2.z, ho.z);
                hv.w = gruc(i0.w+h0.w, i1.w+h1.w, i2.w, h2.w, ho.w);
                hs4[m] = hv;
            }
            __syncthreads();
        }
        if (isgen){
            while (gk < GQ4){
                int blk = gw + NGW*gk;
                if (blk >= GBLK3){ gk = GQ6; break; }
                gen_prefetch(gw + NGW*(gk+1), (gk & 1) ? slotA : slotB, ow, lane);
                asm volatile("cp.async.wait_group 1;" ::: "memory");
                __syncwarp();
                gen_compute3(blk, smem + SM_WBUF + (wid*2 + (gk&1))*(3*H),
                             hs4, ob, lane, zm, zs);
                gk++;
            }
        } else {
            for (int k = 0;; k++){
                int task = dw + NGW*k;
                if (task >= 3072) break;
                int is_th = (task >= 1536);
                int tt = is_th ? task - 1536 : task;
                int bh = tt & 1, j = tt >> 1;
                int b0 = bh*4;
                const ulonglong2* r2 = (const ulonglong2*)((is_th ? aw4 : cw4) + (size_t)j*H4);
                const ulonglong2* HS = (const ulonglong2*)hs4;
                unsigned long long a0=0ull, a1=0ull, a2=0ull, a3=0ull;
                #pragma unroll
                for (int i = 0; i < 6; i++){
                    ulonglong2 w = r2[i*32 + lane];
                    ulonglong2 h0 = HS[(b0+0)*H4 + i*32 + lane];
                    ulonglong2 h1 = HS[(b0+1)*H4 + i*32 + lane];
                    ulonglong2 h2 = HS[(b0+2)*H4 + i*32 + lane];
                    ulonglong2 h3 = HS[(b0+3)*H4 + i*32 + lane];
                    a0 = ffma2(w.x, h0.x, a0); a0 = ffma2(w.y, h0.y, a0);
                    a1 = ffma2(w.x, h1.x, a1); a1 = ffma2(w.y, h1.y, a1);
                    a2 = ffma2(w.x, h2.x, a2); a2 = ffma2(w.y, h2.y, a2);
                    a3 = ffma2(w.x, h3.x, a3); a3 = ffma2(w.y, h3.y, a3);
                }
                float f0 = wred(hadd2(a0)), f1 = wred(hadd2(a1));
                float f2 = wred(hadd2(a2)), f3 = wred(hadd2(a3));
                if (!lane){
                    float bb = is_th ? ab[j] : cb[j];
                    float* dst = is_th ? g_th : g_th2;
                    dst[(b0+0)*H + j] = f0 + bb;
                    dst[(b0+1)*H + j] = f1 + bb;
                    dst[(b0+2)*H + j] = f2 + bb;
                    dst[(b0+3)*H + j] = f3 + bb;
                }
            }
        }
        gridbar(bt);

        // ===== P5: gen warps: k<GQ5 | dot warps: css (4096, th2 from L2)
        if (isgen){
            while (gk < GQ5){
                int blk = gw + NGW*gk;
                if (blk >= GBLK3){ gk = GQ6; break; }
                gen_prefetch(gw + NGW*(gk+1), (gk & 1) ? slotA : slotB, ow, lane);
                asm volatile("cp.async.wait_group 1;" ::: "memory");
                __syncwarp();
                gen_compute3(blk, smem + SM_WBUF + (wid*2 + (gk&1))*(3*H),
                             hs4, ob, lane, zm, zs);
                gk++;
            }
        } else {
            for (int k = 0;; k++){
                int task = dw + NGW*k;
                if (task >= 4096) break;
                int b = task >> 9, s = task & 511;
                float a = dot768_2(enc + ((size_t)b*SEQ + s)*H, g_th2 + b*H, lane);
                if (!lane) g_css[b*SEQ + s] = a;
            }
        }
        gridbar(bt);

        // ===== P6: gen warps: rest | dot warps: copy-chain (128); CTA Z combine
        if (isgen){
            while (gk < GQ6){
                int blk = gw + NGW*gk;
                if (blk >= GBLK3) break;
                gen_prefetch(gw + NGW*(gk+1), (gk & 1) ? slotA : slotB, ow, lane);
                asm volatile("cp.async.wait_group 1;" ::: "memory");
                __syncwarp();
                gen_compute3(blk, smem + SM_WBUF + (wid*2 + (gk&1))*(3*H),
                             hs4, ob, lane, zm, zs);
                gk++;
            }
            asm volatile("cp.async.wait_group 0;" ::: "memory");
        } else {
            if (dw < 128){
                int b = dw >> 4, ch = dw & 15;
                int s = ch*32 + lane;
                float cm = MNEG, cs = 0.f;
                if (g_fo[b*SEQ + s]){
                    int tok = inputs[b*SEQ + s];
                    const int* ip = inputs + b*SEQ;
                    const float* cp = g_css + b*SEQ;
                    float sum = 0.f;
                    for (int s2 = 0; s2 < SEQ; s2++)
                        if (ip[s2] == tok) sum += cp[s2];
                    g_copyval[b*VOC + tok] = sum;
                    pmerge1(cm, cs, sum);
                }
                pshfl_reduce(cm, cs, 16);
                pshfl_reduce(cm, cs, 8);
                pshfl_reduce(cm, cs, 4);
                pshfl_reduce(cm, cs, 2);
                pshfl_reduce(cm, cs, 1);
                if (lane == b) pmergep(zm, zs, cm, cs);
            }
        }
        pshfl_reduce(zm, zs, 8);
        pshfl_reduce(zm, zs, 16);
        if (lane < 8) zsm[wid*8 + lane] = make_float2(zm, zs);
        __syncthreads();
        if (wid < 8){
            float2 p = (lane < NWARP) ? zsm[lane*8 + wid] : make_float2(MNEG, 0.f);
            float m = p.x, s = p.y;
            pshfl_reduce(m, s, 16);
            pshfl_reduce(m, s, 8);
            pshfl_reduce(m, s, 4);
            pshfl_reduce(m, s, 2);
            pshfl_reduce(m, s, 1);
            if (!lane) g_Zp2[cta][wid] = make_float2(m, s);
        }
        gridbar(bt);

        // ===== P7: global Z combine; log-prob row + argmax
        //          (rebalanced: 2 threads per vocab element, 4 batches each)
        {
            if (tid < 8) bkey[tid] = 0ull;
            if (wid < 8){
                float m = MNEG, s = 0.f;
                for (int i = lane; i < NCTA; i += 32){
                    float2 p = g_Zp2[i][wid];
                    pmergep(m, s, p.x, p.y);
                }
                pshfl_reduce(m, s, 16);
                pshfl_reduce(m, s, 8);
                pshfl_reduce(m, s, 4);
                pshfl_reduce(m, s, 2);
                pshfl_reduce(m, s, 1);
                if (!lane){ msh[wid] = m; zinv[wid] = 1.f/s; }
            }
            __syncthreads();
            int v0 = cta*ZCH;
            int cnt = min(ZCH, VOC - v0);
            int idx = tid >> 1, half = tid & 1;
            if (idx < cnt){
                int v = v0 + idx;
                int b0 = half*4;
                float4 a = ((const float4*)g_gen)[(size_t)v*2 + half];
                float gv[4] = {a.x, a.y, a.z, a.w};
                unsigned int vk = (unsigned int)(0x7FFFFFFF - v);
                #pragma unroll
                for (int bq = 0; bq < 4; bq++){
                    int b = b0 + bq;
                    float p = __expf(gv[bq] - msh[b])*zinv[b];
                    if (g_present[b*VOC + v])
                        p += __expf(g_copyval[b*VOC + v] - msh[b])*zinv[b];
                    float lp = __logf(p + 1e-10f);
                    stcs(out + ((size_t)b*TMAXX + t)*EXT + v, lp);
                    unsigned long long key = (((unsigned long long)okey(lp)) << 32) | vk;
                    atomicMax(&bkey[b], key);
                }
            }
            __syncthreads();
            if (tid < 8) atomicMax(&g_amax2[tid], bkey[tid]);
        }
        gridbar(bt);
    }

    if (cta == 0 && tid < 8 && has_tail){
        unsigned long long key = g_amax2[tid];
        int samp = 0x7FFFFFFF - (int)(unsigned int)(key & 0xFFFFFFFFull);
        out[D1 + tid*TMAXX + (TMAXX - 1)] = (float)samp;
    }
}

// ---------------- host ----------------
extern "C" void kernel_launch(void* const* d_in, const int* in_sizes, int n_in,
                              void* d_out, int out_size){
    const float* enc    = (const float*)d_in[0];
    const int*   inputs = (const int*)  d_in[1];
    const int*   cls    = (const int*)  d_in[2];
    /* d_in[3] sep_to unused */
    const float* emb    = (const float*)d_in[4];
    const float* aw     = (const float*)d_in[5];
    const float* ab     = (const float*)d_in[6];
    const float* cw     = (const float*)d_in[7];
    const float* cb     = (const float*)d_in[8];
    const float* wih    = (const float*)d_in[9];
    const float* whh    = (const float*)d_in[10];
    const float* bih    = (const float*)d_in[11];
    const float* bhh    = (const float*)d_in[12];
    const float* ow     = (const float*)d_in[13];
    const float* ob     = (const float*)d_in[14];
    float* out = (float*)d_out;
    int has_tail = (out_size >= D1 + BATCH*TMAXX) ? 1 : 0;

    const int smemsz = SM_TOTF*sizeof(float);   // 221184 B
    cudaFuncSetAttribute(k_loop, cudaFuncAttributeMaxDynamicSharedMemorySize, smemsz);

    k_init<<<512, 256>>>(cls, emb, ab, inputs, out, has_tail);
    k_loop<<<NCTA, NTHR, smemsz>>>(enc, inputs, emb,
                                   (const float4*)aw, ab,
                                   (const float4*)cw, cb,
                                   (const float4*)wih, (const float4*)whh,
                                   bih, bhh,
                                   ow, ob,
                                   out, has_tail);
}